// round 2
// baseline (speedup 1.0000x reference)
#include <cuda_runtime.h>
#include <cstdint>

#define PRNG_PARTITIONABLE 1
#define NPAP 4096
#define NAUT 2048
#define HD   128

// ---------------- threefry2x32 (JAX, 20 rounds) ----------------
__host__ __device__ __forceinline__ void tf2x32(unsigned k0, unsigned k1,
                                                unsigned x0, unsigned x1,
                                                unsigned &o0, unsigned &o1) {
  unsigned ks2 = k0 ^ k1 ^ 0x1BD11BDAu;
  x0 += k0; x1 += k1;
#define TFR(r) { x0 += x1; x1 = (x1 << (r)) | (x1 >> (32 - (r))); x1 ^= x0; }
  TFR(13) TFR(15) TFR(26) TFR(6)  x0 += k1;  x1 += ks2 + 1u;
  TFR(17) TFR(29) TFR(16) TFR(24) x0 += ks2; x1 += k0 + 2u;
  TFR(13) TFR(15) TFR(26) TFR(6)  x0 += k0;  x1 += k1 + 3u;
  TFR(17) TFR(29) TFR(16) TFR(24) x0 += k1;  x1 += ks2 + 4u;
  TFR(13) TFR(15) TFR(26) TFR(6)  x0 += ks2; x1 += k0 + 5u;
#undef TFR
  o0 = x0; o1 = x1;
}

__device__ __forceinline__ unsigned jax_bits(unsigned k0, unsigned k1,
                                             unsigned m, unsigned S) {
#if PRNG_PARTITIONABLE
  unsigned o0, o1; tf2x32(k0, k1, 0u, m, o0, o1); return o0 ^ o1;
#else
  unsigned half = S >> 1, o0, o1;
  if (m < half) { tf2x32(k0, k1, m, m + half, o0, o1); return o0; }
  tf2x32(k0, k1, m - half, m, o0, o1); return o1;
#endif
}

// ---------------- scratch arena ----------------
__device__ __align__(256) unsigned char g_arena[28u * 1024u * 1024u];

// ---------------- CSR build ----------------
__global__ void zero_int_kernel(int* p, int n) {
  int i = blockIdx.x * blockDim.x + threadIdx.x;
  if (i < n) p[i] = 0;
}
__global__ void count_kernel(const int* __restrict__ key, int E, int* cnt) {
  int e = blockIdx.x * blockDim.x + threadIdx.x;
  if (e < E) atomicAdd(&cnt[key[e]], 1);
}
struct ScanArgs { const int* cnt[6]; int* off[6]; int n[6]; };
__global__ void scan_kernel(ScanArgs a) {
  int b = blockIdx.x;
  const int* cnt = a.cnt[b]; int* off = a.off[b]; int n = a.n[b];
  __shared__ int part[256];
  int t = threadIdx.x, chunk = (n + 255) / 256, st = t * chunk, s = 0;
  for (int j = 0; j < chunk; j++) { int i = st + j; if (i < n) s += cnt[i]; }
  part[t] = s; __syncthreads();
  for (int d = 1; d < 256; d <<= 1) {
    int v = (t >= d) ? part[t - d] : 0;
    __syncthreads(); part[t] += v; __syncthreads();
  }
  int run = (t == 0) ? 0 : part[t - 1];
  for (int j = 0; j < chunk; j++) {
    int i = st + j;
    if (i < n) { off[i] = run; run += cnt[i]; }
  }
  if (t == 255) off[n] = part[255];
}
__global__ void fill_kernel(const int* __restrict__ key, int E,
                            const int* __restrict__ off, int* cur, int* list) {
  int e = blockIdx.x * blockDim.x + threadIdx.x;
  if (e < E) { int k = key[e]; int p = atomicAdd(&cur[k], 1); list[off[k] + p] = e; }
}

// ---------------- GEMM C[M,N]=A@B (bit0: C+=, bit1: relu) ----------------
__global__ __launch_bounds__(256) void gemm64(const float* __restrict__ A,
                                              const float* __restrict__ B,
                                              float* __restrict__ C,
                                              int M, int N, int K, int flags) {
  __shared__ float As[16][64];
  __shared__ float Bs[16][68];
  int tid = threadIdx.x, tx = tid & 15, ty = tid >> 4;
  int bm = blockIdx.y * 64, bn = blockIdx.x * 64;
  float acc[4][4] = {};
  for (int kt = 0; kt < K; kt += 16) {
    {
      int m = tid >> 2, kk = (tid & 3) * 4;
      float4 v = *(const float4*)(A + (size_t)(bm + m) * K + kt + kk);
      As[kk][m] = v.x; As[kk + 1][m] = v.y; As[kk + 2][m] = v.z; As[kk + 3][m] = v.w;
    }
    {
      int kk = tid >> 4, n0 = (tid & 15) * 4;
      float4 v = *(const float4*)(B + (size_t)(kt + kk) * N + bn + n0);
      Bs[kk][n0] = v.x; Bs[kk][n0 + 1] = v.y; Bs[kk][n0 + 2] = v.z; Bs[kk][n0 + 3] = v.w;
    }
    __syncthreads();
#pragma unroll
    for (int k = 0; k < 16; k++) {
      float a[4], b[4];
#pragma unroll
      for (int i = 0; i < 4; i++) a[i] = As[k][ty * 4 + i];
#pragma unroll
      for (int j = 0; j < 4; j++) b[j] = Bs[k][tx * 4 + j];
#pragma unroll
      for (int i = 0; i < 4; i++)
#pragma unroll
        for (int j = 0; j < 4; j++) acc[i][j] += a[i] * b[j];
    }
    __syncthreads();
  }
#pragma unroll
  for (int i = 0; i < 4; i++) {
    int row = bm + ty * 4 + i;
#pragma unroll
    for (int j = 0; j < 4; j++) {
      int col = bn + tx * 4 + j;
      float v = acc[i][j];
      if (flags & 1) v += C[(size_t)row * N + col];
      if (flags & 2) v = fmaxf(v, 0.f);
      C[(size_t)row * N + col] = v;
    }
  }
}

// ---------------- CSR weighted-mean gather, warp/node ----------------
__global__ __launch_bounds__(256) void gather_mean(const int* __restrict__ off,
                                                   const int* __restrict__ list,
                                                   const int* __restrict__ srcArr,
                                                   const float* __restrict__ w,
                                                   const float* __restrict__ Hf,
                                                   float* __restrict__ out, int nNodes) {
  int node = blockIdx.x * 8 + (threadIdx.x >> 5);
  if (node >= nNodes) return;
  int lane = threadIdx.x & 31;
  int b = off[node], e = off[node + 1];
  float4 acc = make_float4(0.f, 0.f, 0.f, 0.f);
  for (int idx = b; idx < e; ++idx) {
    int eid = list[idx];
    int s = srcArr[eid];
    float wt = w ? w[eid] : 1.f;
    float4 v = *((const float4*)(Hf + (size_t)s * HD) + lane);
    acc.x += wt * v.x; acc.y += wt * v.y; acc.z += wt * v.z; acc.w += wt * v.w;
  }
  float inv = 1.f / fmaxf((float)(e - b), 1.f);
  acc.x *= inv; acc.y *= inv; acc.z *= inv; acc.w *= inv;
  *((float4*)(out + (size_t)node * HD) + lane) = acc;
}

// ---------------- prune: edge MLP + coalesce + gumbel top-5 ----------------
__device__ __forceinline__ unsigned long long packkey(float v, int j) {
  unsigned u = __float_as_uint(v);
  u = (u >> 31) ? ~u : (u | 0x80000000u);
  return (((unsigned long long)u) << 32) |
         (unsigned long long)(0xFFFFFFFFu - (unsigned)j);
}

__global__ __launch_bounds__(128) void prune_kernel(
    const int* __restrict__ roff, const int* __restrict__ rlist,
    const int* __restrict__ dstArr,
    const float* __restrict__ U, const float* __restrict__ V,
    const float* __restrict__ b1, const float* __restrict__ W2,
    const float* __restrict__ b2,
    int Nc, unsigned k0, unsigned k1, int* __restrict__ sel) {
  extern __shared__ float sm[];
  float* Arow = sm;          // Nc
  float* Urow = sm + Nc;     // 256
  float* W2c  = Urow + 256;  // 256
  __shared__ unsigned long long red[4];
  int i = blockIdx.x, t = threadIdx.x;
  for (int c = t; c < 256; c += 128) {
    Urow[c] = U[(size_t)i * 256 + c] + b1[c];
    W2c[c]  = W2[2 * c];
  }
  for (int j = t; j < Nc; j += 128) Arow[j] = 0.f;
  __syncthreads();

  int b = roff[i], nE = roff[i + 1] - b;
  int warp = t >> 5, lane = t & 31;
  float b2v = b2[0];
  for (int e = warp; e < nE; e += 4) {
    int eid = rlist[b + e];
    int d = dstArr[eid];
    const float* Vd = V + (size_t)d * 256;
    float acc = 0.f;
#pragma unroll
    for (int c = lane; c < 256; c += 32)
      acc += fmaxf(Urow[c] + Vd[c], 0.f) * W2c[c];
#pragma unroll
    for (int o = 16; o; o >>= 1) acc += __shfl_xor_sync(0xffffffffu, acc, o);
    if (lane == 0) atomicAdd(&Arow[d], acc + b2v);
  }
  __syncthreads();

  unsigned S = (unsigned)Nc * (unsigned)Nc;
  for (int j = t; j < Nc; j += 128) {
    float a = Arow[j];
    if (a > 0.f) {
      unsigned m = (unsigned)i * (unsigned)Nc + (unsigned)j;
      unsigned bits = jax_bits(k0, k1, m, S);
      float f = __uint_as_float((bits >> 9) | 0x3f800000u) - 1.0f;
      float u = fmaxf(1e-10f, f + 1e-10f);
      Arow[j] = a + (-logf(-logf(u)));
    } else {
      Arow[j] = -1e9f;
    }
  }
  __syncthreads();

  for (int r = 0; r < 5; r++) {
    unsigned long long best = 0ull;
    for (int j = t; j < Nc; j += 128) {
      unsigned long long k = packkey(Arow[j], j);
      if (k > best) best = k;
    }
#pragma unroll
    for (int o = 16; o; o >>= 1) {
      unsigned long long v = __shfl_xor_sync(0xffffffffu, best, o);
      if (v > best) best = v;
    }
    if (lane == 0) red[warp] = best;
    __syncthreads();
    if (t == 0) {
      unsigned long long w0 = red[0];
      for (int q = 1; q < 4; q++) if (red[q] > w0) w0 = red[q];
      int j = (int)(0xFFFFFFFFu - (unsigned)(w0 & 0xFFFFFFFFull));
      sel[i * 5 + r] = j;
      Arow[j] = -3.0e38f;
    }
    __syncthreads();
  }
}

__global__ void w_kernel(const int* __restrict__ src, const int* __restrict__ dst,
                         const int* __restrict__ sel, int E,
                         float* __restrict__ w, float* __restrict__ wout) {
  int e = blockIdx.x * blockDim.x + threadIdx.x;
  if (e < E) {
    int s = src[e], d = dst[e];
    const int* sp = &sel[s * 5];
    float v = (sp[0] == d || sp[1] == d || sp[2] == d || sp[3] == d || sp[4] == d)
                  ? 1.f : 0.f;
    w[e] = v;
    if (wout) wout[e] = v;
  }
}

// ---------------- GNN2 layer1 for the single output node + classify ----------------
__global__ __launch_bounds__(128) void node_out_kernel(
    const int* __restrict__ idxPtr,
    const float* __restrict__ HP0, const float* __restrict__ HA0,
    const int* __restrict__ ppoff, const int* __restrict__ pplist,
    const int* __restrict__ ppsrc, const float* __restrict__ wpp,
    const int* __restrict__ apoff, const int* __restrict__ aplist,
    const int* __restrict__ apsrc,
    const float* __restrict__ Wself, const float* __restrict__ Wpp1,
    const float* __restrict__ Wap1,
    const float* __restrict__ Wc, const float* __restrict__ bc,
    float* __restrict__ out) {
  __shared__ float selfv[128], mpp[128], mapv[128], agg[128];
  int t = threadIdx.x;
  int idx = idxPtr[0];
  selfv[t] = HP0[(size_t)idx * HD + t];
  int b = ppoff[idx], e = ppoff[idx + 1];
  float s = 0.f;
  for (int q = b; q < e; q++) {
    int eid = pplist[q];
    s += wpp[eid] * HP0[(size_t)ppsrc[eid] * HD + t];
  }
  mpp[t] = s / fmaxf((float)(e - b), 1.f);
  b = apoff[idx]; e = apoff[idx + 1];
  s = 0.f;
  for (int q = b; q < e; q++) {
    int eid = aplist[q];
    s += HA0[(size_t)apsrc[eid] * HD + t];
  }
  mapv[t] = s / fmaxf((float)(e - b), 1.f);
  __syncthreads();
  float a = 0.f;
  for (int k = 0; k < HD; k++)
    a += selfv[k] * Wself[k * HD + t] + mpp[k] * Wpp1[k * HD + t] +
         mapv[k] * Wap1[k * HD + t];
  agg[t] = fmaxf(a, 0.f);
  __syncthreads();
  if (t < 5) {
    float y = bc[t];
    for (int k = 0; k < HD; k++) y += agg[k] * Wc[k * 5 + t];
    out[t] = y;
  }
}

// ---------------- host launcher ----------------
extern "C" void kernel_launch(void* const* d_in, const int* in_sizes, int n_in,
                              void* d_out, int out_size) {
  const float* x_p = (const float*)d_in[0];
  const float* x_a = (const float*)d_in[1];
  const int* ei_pp = (const int*)d_in[2];
  const int* ei_aa = (const int*)d_in[3];
  const int* ei_pa = (const int*)d_in[4];
  const int* ei_ap = (const int*)d_in[5];
  const int* idxPtr = (const int*)d_in[8];
  const float* Ws_p0 = (const float*)d_in[9];
  const float* Ws_p1 = (const float*)d_in[10];
  const float* Ws_a0 = (const float*)d_in[11];
  const float* Ws_a1 = (const float*)d_in[12];
  const float* Wpp0 = (const float*)d_in[13];
  const float* Wpp1 = (const float*)d_in[14];
  const float* Waa0 = (const float*)d_in[15];
  const float* Waa1 = (const float*)d_in[16];
  const float* Wpa0 = (const float*)d_in[17];
  const float* Wap0 = (const float*)d_in[19];
  const float* Wap1 = (const float*)d_in[20];
  const float* Wep1_pp = (const float*)d_in[21];
  const float* bep1_pp = (const float*)d_in[22];
  const float* Wep2_pp = (const float*)d_in[23];
  const float* bep2_pp = (const float*)d_in[24];
  const float* Wep1_aa = (const float*)d_in[25];
  const float* bep1_aa = (const float*)d_in[26];
  const float* Wep2_aa = (const float*)d_in[27];
  const float* bep2_aa = (const float*)d_in[28];
  const float* Wc = (const float*)d_in[29];
  const float* bc = (const float*)d_in[30];

  int Epp = in_sizes[2] / 2, Eaa = in_sizes[3] / 2;
  int Epa = in_sizes[4] / 2, Eap = in_sizes[5] / 2;
  const int* pp_src = ei_pp;       const int* pp_dst = ei_pp + Epp;
  const int* aa_src = ei_aa;       const int* aa_dst = ei_aa + Eaa;
  const int* pa_src = ei_pa;       const int* pa_dst = ei_pa + Epa;
  const int* ap_src = ei_ap;       const int* ap_dst = ei_ap + Eap;

  // split keys of jax.random.key(42)
  unsigned kpp0, kpp1, kaa0, kaa1;
#if PRNG_PARTITIONABLE
  tf2x32(0u, 42u, 0u, 0u, kpp0, kpp1);
  tf2x32(0u, 42u, 0u, 1u, kaa0, kaa1);
#else
  {
    unsigned a0, a1, b0, b1;
    tf2x32(0u, 42u, 0u, 2u, a0, a1);
    tf2x32(0u, 42u, 1u, 3u, b0, b1);
    kpp0 = a0; kpp1 = b0; kaa0 = a1; kaa1 = b1;
  }
#endif

  void* basep = nullptr;
  cudaGetSymbolAddress(&basep, g_arena);
  unsigned char* ar = (unsigned char*)basep;
  size_t off = 0;
  auto carve = [&](size_t bytes) -> unsigned char* {
    unsigned char* p = ar + off;
    off += (bytes + 255) & ~(size_t)255;
    return p;
  };
  float* AGGP = (float*)carve((size_t)NPAP * HD * 4);
  float* AGGA = (float*)carve((size_t)NAUT * HD * 4);
  float* HP0 = (float*)carve((size_t)NPAP * HD * 4);
  float* HP1 = (float*)carve((size_t)NPAP * HD * 4);
  float* HA0 = (float*)carve((size_t)NAUT * HD * 4);
  float* HA1 = (float*)carve((size_t)NAUT * HD * 4);
  float* UP = (float*)carve((size_t)NPAP * 256 * 4);
  float* VP = (float*)carve((size_t)NPAP * 256 * 4);
  float* UA = (float*)carve((size_t)NAUT * 256 * 4);
  float* VA = (float*)carve((size_t)NAUT * 256 * 4);
  float* WPP = (float*)carve((size_t)Epp * 4);
  float* WAA = (float*)carve((size_t)Eaa * 4);
  int* CNT = (int*)carve(6 * 4096 * 4);
  int* CUR = (int*)carve(6 * 4096 * 4);
  int* OFF = (int*)carve(6 * 4097 * 4);
  int* L_PPD = (int*)carve((size_t)Epp * 4);
  int* L_PPS = (int*)carve((size_t)Epp * 4);
  int* L_AAD = (int*)carve((size_t)Eaa * 4);
  int* L_AAS = (int*)carve((size_t)Eaa * 4);
  int* L_PAD = (int*)carve((size_t)Epa * 4);
  int* L_APD = (int*)carve((size_t)Eap * 4);
  int* SELPP = (int*)carve((size_t)NPAP * 5 * 4);
  int* SELAA = (int*)carve((size_t)NAUT * 5 * 4);

  const int* keys[6] = {pp_dst, pp_src, aa_dst, aa_src, pa_dst, ap_dst};
  int ns[6] = {NPAP, NPAP, NAUT, NAUT, NAUT, NPAP};
  int Es[6] = {Epp, Epp, Eaa, Eaa, Epa, Eap};
  int* lists[6] = {L_PPD, L_PPS, L_AAD, L_AAS, L_PAD, L_APD};

  { int n = 6 * 4096 * 2; zero_int_kernel<<<(n + 255) / 256, 256>>>(CNT, n); }
  for (int r = 0; r < 6; r++)
    count_kernel<<<(Es[r] + 255) / 256, 256>>>(keys[r], Es[r], CNT + r * 4096);
  {
    ScanArgs sa;
    for (int r = 0; r < 6; r++) {
      sa.cnt[r] = CNT + r * 4096; sa.off[r] = OFF + r * 4097; sa.n[r] = ns[r];
    }
    scan_kernel<<<6, 256>>>(sa);
  }
  for (int r = 0; r < 6; r++)
    fill_kernel<<<(Es[r] + 255) / 256, 256>>>(keys[r], Es[r], OFF + r * 4097,
                                              CUR + r * 4096, lists[r]);

  auto gemm = [&](const float* A, const float* B, float* C, int M, int N, int K,
                  int flags) {
    dim3 g(N / 64, M / 64);
    gemm64<<<g, 256>>>(A, B, C, M, N, K, flags);
  };
  auto gather = [&](int csr, const int* srcArr, const float* w, const float* Hf,
                    float* out_, int n) {
    gather_mean<<<(n + 7) / 8, 256>>>(OFF + csr * 4097, lists[csr], srcArr, w, Hf,
                                      out_, n);
  };

  // ---- GNN1 (single=True) ----
  gather(0, pp_src, nullptr, x_p, AGGP, NPAP);
  gemm(x_p, Ws_p0, HP0, NPAP, HD, HD, 0);
  gemm(AGGP, Wpp0, HP0, NPAP, HD, HD, 3);
  gather(2, aa_src, nullptr, x_a, AGGA, NAUT);
  gemm(x_a, Ws_a0, HA0, NAUT, HD, HD, 0);
  gemm(AGGA, Waa0, HA0, NAUT, HD, HD, 3);
  gather(0, pp_src, nullptr, HP0, AGGP, NPAP);
  gemm(HP0, Ws_p1, HP1, NPAP, HD, HD, 0);
  gemm(AGGP, Wpp1, HP1, NPAP, HD, HD, 3);
  gather(2, aa_src, nullptr, HA0, AGGA, NAUT);
  gemm(HA0, Ws_a1, HA1, NAUT, HD, HD, 0);
  gemm(AGGA, Waa1, HA1, NAUT, HD, HD, 3);

  // ---- edge-MLP node projections ----
  gemm(HP1, Wep1_pp, UP, NPAP, 256, HD, 0);
  gemm(HP1, Wep1_pp + 128 * 256, VP, NPAP, 256, HD, 0);
  gemm(HA1, Wep1_aa, UA, NAUT, 256, HD, 0);
  gemm(HA1, Wep1_aa + 128 * 256, VA, NAUT, 256, HD, 0);

  // ---- prune (per-src-row gumbel top-5) ----
  prune_kernel<<<NPAP, 128, (4096 + 512) * sizeof(float)>>>(
      OFF + 1 * 4097, L_PPS, pp_dst, UP, VP, bep1_pp, Wep2_pp, bep2_pp,
      4096, kpp0, kpp1, SELPP);
  prune_kernel<<<NAUT, 128, (2048 + 512) * sizeof(float)>>>(
      OFF + 3 * 4097, L_AAS, aa_dst, UA, VA, bep1_aa, Wep2_aa, bep2_aa,
      2048, kaa0, kaa1, SELAA);

  // ---- edge weights (also write output segments) ----
  float* out_f = (float*)d_out;
  float* out_wpp = (out_size >= 5 + Epp) ? out_f + 5 : nullptr;
  float* out_waa = (out_size >= 5 + Epp + Eaa) ? out_f + 5 + Epp : nullptr;
  w_kernel<<<(Epp + 255) / 256, 256>>>(pp_src, pp_dst, SELPP, Epp, WPP, out_wpp);
  w_kernel<<<(Eaa + 255) / 256, 256>>>(aa_src, aa_dst, SELAA, Eaa, WAA, out_waa);

  // ---- GNN2 layer 0 (full graph, edge_attn on pp/aa) ----
  gather(0, pp_src, WPP, x_p, AGGP, NPAP);
  gemm(x_p, Ws_p0, HP0, NPAP, HD, HD, 0);
  gemm(AGGP, Wpp0, HP0, NPAP, HD, HD, 1);
  gather(5, ap_src, nullptr, x_a, AGGP, NPAP);
  gemm(AGGP, Wap0, HP0, NPAP, HD, HD, 3);
  gather(2, aa_src, WAA, x_a, AGGA, NAUT);
  gemm(x_a, Ws_a0, HA0, NAUT, HD, HD, 0);
  gemm(AGGA, Waa0, HA0, NAUT, HD, HD, 1);
  gather(4, pa_src, nullptr, x_p, AGGA, NAUT);
  gemm(AGGA, Wpa0, HA0, NAUT, HD, HD, 3);

  // ---- GNN2 layer 1 only for node `index`, then classifier ----
  node_out_kernel<<<1, 128>>>(idxPtr, HP0, HA0,
                              OFF + 0 * 4097, L_PPD, pp_src, WPP,
                              OFF + 5 * 4097, L_APD, ap_src,
                              Ws_p1, Wpp1, Wap1, Wc, bc, out_f);
}

// round 3
// speedup vs baseline: 1.3675x; 1.3675x over previous
#include <cuda_runtime.h>
#include <cstdint>

#define NPAP 4096
#define NAUT 2048
#define HD   128

// ---------------- threefry2x32 (JAX, 20 rounds) ----------------
__host__ __device__ __forceinline__ void tf2x32(unsigned k0, unsigned k1,
                                                unsigned x0, unsigned x1,
                                                unsigned &o0, unsigned &o1) {
  unsigned ks2 = k0 ^ k1 ^ 0x1BD11BDAu;
  x0 += k0; x1 += k1;
#define TFR(r) { x0 += x1; x1 = (x1 << (r)) | (x1 >> (32 - (r))); x1 ^= x0; }
  TFR(13) TFR(15) TFR(26) TFR(6)  x0 += k1;  x1 += ks2 + 1u;
  TFR(17) TFR(29) TFR(16) TFR(24) x0 += ks2; x1 += k0 + 2u;
  TFR(13) TFR(15) TFR(26) TFR(6)  x0 += k0;  x1 += k1 + 3u;
  TFR(17) TFR(29) TFR(16) TFR(24) x0 += k1;  x1 += ks2 + 4u;
  TFR(13) TFR(15) TFR(26) TFR(6)  x0 += ks2; x1 += k0 + 5u;
#undef TFR
  o0 = x0; o1 = x1;
}
__device__ __forceinline__ unsigned jax_bits(unsigned k0, unsigned k1, unsigned m) {
  unsigned o0, o1; tf2x32(k0, k1, 0u, m, o0, o1); return o0 ^ o1;
}

// ---------------- scratch arena ----------------
__device__ __align__(256) unsigned char g_arena[32u * 1024u * 1024u];

// ---------------- CSR build (fused) ----------------
__global__ void zero_int_kernel(int* p, int n) {
  int i = blockIdx.x * blockDim.x + threadIdx.x;
  if (i < n) p[i] = 0;
}
struct EdgeJobs {
  const int* key[6]; const int* part[6];
  const int* off[6]; int* cnt[6]; int* cur[6]; int* out[6];
  int eStart[7];
};
__global__ void count_all(EdgeJobs ej, int total) {
  int g = blockIdx.x * blockDim.x + threadIdx.x;
  if (g >= total) return;
  int r = 0;
  while (g >= ej.eStart[r + 1]) r++;
  atomicAdd(&ej.cnt[r][ej.key[r][g - ej.eStart[r]]], 1);
}
__global__ void fill_all(EdgeJobs ej, int total) {
  int g = blockIdx.x * blockDim.x + threadIdx.x;
  if (g >= total) return;
  int r = 0;
  while (g >= ej.eStart[r + 1]) r++;
  int e = g - ej.eStart[r];
  int k = ej.key[r][e];
  int p = atomicAdd(&ej.cur[r][k], 1);
  ej.out[r][ej.off[r][k] + p] = ej.part[r][e];
}
struct ScanArgs { const int* cnt[6]; int* off[6]; int n[6]; };
__global__ void scan_kernel(ScanArgs a) {
  int b = blockIdx.x;
  const int* cnt = a.cnt[b]; int* off = a.off[b]; int n = a.n[b];
  __shared__ int part[256];
  int t = threadIdx.x, chunk = (n + 255) / 256, st = t * chunk, s = 0;
  for (int j = 0; j < chunk; j++) { int i = st + j; if (i < n) s += cnt[i]; }
  part[t] = s; __syncthreads();
  for (int d = 1; d < 256; d <<= 1) {
    int v = (t >= d) ? part[t - d] : 0;
    __syncthreads(); part[t] += v; __syncthreads();
  }
  int run = (t == 0) ? 0 : part[t - 1];
  for (int j = 0; j < chunk; j++) {
    int i = st + j;
    if (i < n) { off[i] = run; run += cnt[i]; }
  }
  if (t == 255) off[n] = part[255];
}

// ---------------- multi-job mean gather (optionally sel-weighted) ----------------
struct GJob { const int* off; const int* part; const float* H; float* out;
              const int* sel; int n; };
struct GJobs { GJob j[4]; };
__global__ __launch_bounds__(256) void gather_all(GJobs gj) {
  GJob jb = gj.j[blockIdx.y];
  int node = blockIdx.x * 8 + (threadIdx.x >> 5);
  if (node >= jb.n) return;
  int lane = threadIdx.x & 31;
  int b = jb.off[node], e = jb.off[node + 1];
  float4 acc = make_float4(0.f, 0.f, 0.f, 0.f);
  if (jb.sel) {
    for (int q = b; q < e; ++q) {
      int s = jb.part[q];
      const int* sp = &jb.sel[s * 5];
      if (sp[0] == node || sp[1] == node || sp[2] == node || sp[3] == node ||
          sp[4] == node) {
        float4 v = *((const float4*)(jb.H + (size_t)s * HD) + lane);
        acc.x += v.x; acc.y += v.y; acc.z += v.z; acc.w += v.w;
      }
    }
  } else {
    for (int q = b; q < e; ++q) {
      int s = jb.part[q];
      float4 v = *((const float4*)(jb.H + (size_t)s * HD) + lane);
      acc.x += v.x; acc.y += v.y; acc.z += v.z; acc.w += v.w;
    }
  }
  float inv = 1.f / fmaxf((float)(e - b), 1.f);
  acc.x *= inv; acc.y *= inv; acc.z *= inv; acc.w *= inv;
  *((float4*)(jb.out + (size_t)node * HD) + lane) = acc;
}

// ---------------- multi-job multi-pair GEMM, f32x2, K=128, 64x128 tile ----------------
struct GemmJob { const float* A[3]; const float* B[3]; float* C;
                 int M, N, npairs, relu, rbStart; };
struct GemmJobs { GemmJob j[4]; int njobs; };
__global__ __launch_bounds__(256) void gemm_all(GemmJobs gjs) {
  int by = blockIdx.y;
  int ji = 0;
  while (ji + 1 < gjs.njobs && by >= gjs.j[ji + 1].rbStart) ji++;
  GemmJob jb = gjs.j[ji];
  int row0 = (by - jb.rbStart) * 64;
  int col0 = blockIdx.x * 128;
  if (col0 >= jb.N) return;
  __shared__ float As[16][68];
  __shared__ float Bs[16][132];
  unsigned long long acc[4][4];
#pragma unroll
  for (int i = 0; i < 4; i++)
#pragma unroll
    for (int j = 0; j < 4; j++) acc[i][j] = 0ull;
  int tid = threadIdx.x;
  int ty = tid >> 4;   // 0..15 : rows ty*4..+3
  int tx = tid & 15;   // 0..15 : cols tx*8..+7 (4 pairs)
  for (int p = 0; p < jb.npairs; p++) {
    const float* A = jb.A[p];
    const float* B = jb.B[p];
    for (int kt = 0; kt < 128; kt += 16) {
      {
        int m = tid >> 2, kk = (tid & 3) * 4;
        float4 v = *(const float4*)(A + (size_t)(row0 + m) * 128 + kt + kk);
        As[kk][m] = v.x; As[kk + 1][m] = v.y; As[kk + 2][m] = v.z; As[kk + 3][m] = v.w;
      }
#pragma unroll
      for (int q = 0; q < 2; q++) {
        int li = tid * 2 + q;
        int kk = li >> 5;
        int n4 = (li & 31) * 4;
        float4 v = *(const float4*)(B + (size_t)(kt + kk) * jb.N + col0 + n4);
        Bs[kk][n4] = v.x; Bs[kk][n4 + 1] = v.y; Bs[kk][n4 + 2] = v.z; Bs[kk][n4 + 3] = v.w;
      }
      __syncthreads();
#pragma unroll
      for (int k = 0; k < 16; k++) {
        unsigned long long a2[4], b2[4];
#pragma unroll
        for (int i = 0; i < 4; i++) {
          unsigned ai = __float_as_uint(As[k][ty * 4 + i]);
          asm("mov.b64 %0, {%1, %1};" : "=l"(a2[i]) : "r"(ai));
        }
#pragma unroll
        for (int j = 0; j < 4; j++)
          b2[j] = *(const unsigned long long*)&Bs[k][tx * 8 + j * 2];
#pragma unroll
        for (int i = 0; i < 4; i++)
#pragma unroll
          for (int j = 0; j < 4; j++)
            asm("fma.rn.f32x2 %0, %1, %2, %0;" : "+l"(acc[i][j])
                : "l"(a2[i]), "l"(b2[j]));
      }
      __syncthreads();
    }
  }
#pragma unroll
  for (int i = 0; i < 4; i++) {
    int row = row0 + ty * 4 + i;
#pragma unroll
    for (int j = 0; j < 4; j++) {
      unsigned u0, u1;
      asm("mov.b64 {%0, %1}, %2;" : "=r"(u0), "=r"(u1) : "l"(acc[i][j]));
      float c0 = __uint_as_float(u0), c1 = __uint_as_float(u1);
      if (jb.relu) { c0 = fmaxf(c0, 0.f); c1 = fmaxf(c1, 0.f); }
      float2* cp = (float2*)(jb.C + (size_t)row * jb.N + col0 + tx * 8 + j * 2);
      *cp = make_float2(c0, c1);
    }
  }
}

// ---------------- fused prune (pp rows then aa rows) ----------------
__device__ __forceinline__ unsigned long long packkey(float v, int j) {
  unsigned u = __float_as_uint(v);
  u = (u >> 31) ? ~u : (u | 0x80000000u);
  return (((unsigned long long)u) << 32) |
         (unsigned long long)(0xFFFFFFFFu - (unsigned)j);
}
struct PruneCfg {
  const int* roff; const int* rpart;
  const float* U; const float* V;
  const float* b1; const float* W2; const float* b2;
  int Nc; unsigned k0, k1; int* sel;
};
__global__ __launch_bounds__(128) void prune_all(PruneCfg cp, PruneCfg ca, int nPP) {
  PruneCfg cfg = (blockIdx.x < nPP) ? cp : ca;
  int i = (blockIdx.x < nPP) ? blockIdx.x : (blockIdx.x - nPP);
  extern __shared__ float sm[];
  float* Arow = sm;
  float* Urow = sm + cfg.Nc;
  float* W2c  = Urow + 256;
  __shared__ unsigned long long red[4];
  int t = threadIdx.x;
  for (int c = t; c < 256; c += 128) {
    Urow[c] = cfg.U[(size_t)i * 256 + c] + cfg.b1[c];
    W2c[c]  = cfg.W2[2 * c];
  }
  for (int j = t; j < cfg.Nc; j += 128) Arow[j] = 0.f;
  __syncthreads();

  int b = cfg.roff[i], nE = cfg.roff[i + 1] - b;
  int warp = t >> 5, lane = t & 31;
  float b2v = cfg.b2[0];
  for (int e = warp; e < nE; e += 4) {
    int d = cfg.rpart[b + e];
    const float* Vd = cfg.V + (size_t)d * 256;
    float acc = 0.f;
#pragma unroll
    for (int c = lane; c < 256; c += 32)
      acc += fmaxf(Urow[c] + Vd[c], 0.f) * W2c[c];
#pragma unroll
    for (int o = 16; o; o >>= 1) acc += __shfl_xor_sync(0xffffffffu, acc, o);
    if (lane == 0) atomicAdd(&Arow[d], acc + b2v);
  }
  __syncthreads();

  for (int j = t; j < cfg.Nc; j += 128) {
    float a = Arow[j];
    if (a > 0.f) {
      unsigned m = (unsigned)i * (unsigned)cfg.Nc + (unsigned)j;
      unsigned bits = jax_bits(cfg.k0, cfg.k1, m);
      float f = __uint_as_float((bits >> 9) | 0x3f800000u) - 1.0f;
      float u = fmaxf(1e-10f, f + 1e-10f);
      Arow[j] = a + (-logf(-logf(u)));
    } else {
      Arow[j] = -1e9f;
    }
  }
  __syncthreads();

  for (int r = 0; r < 5; r++) {
    unsigned long long best = 0ull;
    for (int j = t; j < cfg.Nc; j += 128) {
      unsigned long long k = packkey(Arow[j], j);
      if (k > best) best = k;
    }
#pragma unroll
    for (int o = 16; o; o >>= 1) {
      unsigned long long v = __shfl_xor_sync(0xffffffffu, best, o);
      if (v > best) best = v;
    }
    if (lane == 0) red[warp] = best;
    __syncthreads();
    if (t == 0) {
      unsigned long long w0 = red[0];
      for (int q = 1; q < 4; q++) if (red[q] > w0) w0 = red[q];
      int j = (int)(0xFFFFFFFFu - (unsigned)(w0 & 0xFFFFFFFFull));
      cfg.sel[i * 5 + r] = j;
      Arow[j] = -3.0e38f;
    }
    __syncthreads();
  }
}

// ---------------- edge-weight outputs (pp+aa fused) ----------------
__global__ void w_all(const int* __restrict__ pps, const int* __restrict__ ppd,
                      const int* __restrict__ aas, const int* __restrict__ aad,
                      const int* __restrict__ selpp, const int* __restrict__ selaa,
                      int Epp, int Eaa, float* __restrict__ out) {
  int g = blockIdx.x * blockDim.x + threadIdx.x;
  if (g < Epp) {
    int s = pps[g], d = ppd[g];
    const int* sp = &selpp[s * 5];
    out[5 + g] = (sp[0] == d || sp[1] == d || sp[2] == d || sp[3] == d || sp[4] == d)
                     ? 1.f : 0.f;
  } else if (g < Epp + Eaa) {
    int e = g - Epp;
    int s = aas[e], d = aad[e];
    const int* sp = &selaa[s * 5];
    out[5 + Epp + e] = (sp[0] == d || sp[1] == d || sp[2] == d || sp[3] == d ||
                        sp[4] == d) ? 1.f : 0.f;
  }
}

// ---------------- GNN2 layer1 for node `index` + classifier ----------------
__global__ __launch_bounds__(128) void node_out_kernel(
    const int* __restrict__ idxPtr,
    const float* __restrict__ HP0, const float* __restrict__ HA0,
    const int* __restrict__ ppoff, const int* __restrict__ pppart,
    const int* __restrict__ selpp,
    const int* __restrict__ apoff, const int* __restrict__ appart,
    const float* __restrict__ Wself, const float* __restrict__ Wpp1,
    const float* __restrict__ Wap1,
    const float* __restrict__ Wc, const float* __restrict__ bc,
    float* __restrict__ out) {
  __shared__ float selfv[128], mpp[128], mapv[128], agg[128];
  int t = threadIdx.x;
  int idx = idxPtr[0];
  selfv[t] = HP0[(size_t)idx * HD + t];
  int b = ppoff[idx], e = ppoff[idx + 1];
  float s = 0.f;
  for (int q = b; q < e; q++) {
    int sn = pppart[q];
    const int* sp = &selpp[sn * 5];
    if (sp[0] == idx || sp[1] == idx || sp[2] == idx || sp[3] == idx || sp[4] == idx)
      s += HP0[(size_t)sn * HD + t];
  }
  mpp[t] = s / fmaxf((float)(e - b), 1.f);
  b = apoff[idx]; e = apoff[idx + 1];
  s = 0.f;
  for (int q = b; q < e; q++) s += HA0[(size_t)appart[q] * HD + t];
  mapv[t] = s / fmaxf((float)(e - b), 1.f);
  __syncthreads();
  float a = 0.f;
  for (int k = 0; k < HD; k++)
    a += selfv[k] * Wself[k * HD + t] + mpp[k] * Wpp1[k * HD + t] +
         mapv[k] * Wap1[k * HD + t];
  agg[t] = fmaxf(a, 0.f);
  __syncthreads();
  if (t < 5) {
    float y = bc[t];
    for (int k = 0; k < HD; k++) y += agg[k] * Wc[k * 5 + t];
    out[t] = y;
  }
}

// ---------------- host launcher ----------------
extern "C" void kernel_launch(void* const* d_in, const int* in_sizes, int n_in,
                              void* d_out, int out_size) {
  const float* x_p = (const float*)d_in[0];
  const float* x_a = (const float*)d_in[1];
  const int* ei_pp = (const int*)d_in[2];
  const int* ei_aa = (const int*)d_in[3];
  const int* ei_pa = (const int*)d_in[4];
  const int* ei_ap = (const int*)d_in[5];
  const int* idxPtr = (const int*)d_in[8];
  const float* Ws_p0 = (const float*)d_in[9];
  const float* Ws_p1 = (const float*)d_in[10];
  const float* Ws_a0 = (const float*)d_in[11];
  const float* Ws_a1 = (const float*)d_in[12];
  const float* Wpp0 = (const float*)d_in[13];
  const float* Wpp1 = (const float*)d_in[14];
  const float* Waa0 = (const float*)d_in[15];
  const float* Waa1 = (const float*)d_in[16];
  const float* Wpa0 = (const float*)d_in[17];
  const float* Wap0 = (const float*)d_in[19];
  const float* Wap1 = (const float*)d_in[20];
  const float* Wep1_pp = (const float*)d_in[21];
  const float* bep1_pp = (const float*)d_in[22];
  const float* Wep2_pp = (const float*)d_in[23];
  const float* bep2_pp = (const float*)d_in[24];
  const float* Wep1_aa = (const float*)d_in[25];
  const float* bep1_aa = (const float*)d_in[26];
  const float* Wep2_aa = (const float*)d_in[27];
  const float* bep2_aa = (const float*)d_in[28];
  const float* Wc = (const float*)d_in[29];
  const float* bc = (const float*)d_in[30];

  int Epp = in_sizes[2] / 2, Eaa = in_sizes[3] / 2;
  int Epa = in_sizes[4] / 2, Eap = in_sizes[5] / 2;
  const int* pp_src = ei_pp;  const int* pp_dst = ei_pp + Epp;
  const int* aa_src = ei_aa;  const int* aa_dst = ei_aa + Eaa;
  const int* pa_src = ei_pa;  const int* pa_dst = ei_pa + Epa;
  const int* ap_src = ei_ap;  const int* ap_dst = ei_ap + Eap;

  unsigned kpp0, kpp1, kaa0, kaa1;
  tf2x32(0u, 42u, 0u, 0u, kpp0, kpp1);
  tf2x32(0u, 42u, 0u, 1u, kaa0, kaa1);

  void* basep = nullptr;
  cudaGetSymbolAddress(&basep, g_arena);
  unsigned char* ar = (unsigned char*)basep;
  size_t off = 0;
  auto carve = [&](size_t bytes) -> unsigned char* {
    unsigned char* p = ar + off;
    off += (bytes + 255) & ~(size_t)255;
    return p;
  };
  float* AGGP  = (float*)carve((size_t)NPAP * HD * 4);
  float* AGGA  = (float*)carve((size_t)NAUT * HD * 4);
  float* AGGP2 = (float*)carve((size_t)NPAP * HD * 4);
  float* AGGA2 = (float*)carve((size_t)NAUT * HD * 4);
  float* HP0 = (float*)carve((size_t)NPAP * HD * 4);
  float* HP1 = (float*)carve((size_t)NPAP * HD * 4);
  float* HA0 = (float*)carve((size_t)NAUT * HD * 4);
  float* HA1 = (float*)carve((size_t)NAUT * HD * 4);
  float* UP = (float*)carve((size_t)NPAP * 256 * 4);
  float* VP = (float*)carve((size_t)NPAP * 256 * 4);
  float* UA = (float*)carve((size_t)NAUT * 256 * 4);
  float* VA = (float*)carve((size_t)NAUT * 256 * 4);
  int* CNT = (int*)carve(6 * 4096 * 4);
  int* CUR = (int*)carve(6 * 4096 * 4);
  int* OFF = (int*)carve(6 * 4097 * 4);
  int* P0 = (int*)carve((size_t)Epp * 4);   // pp dst-CSR: partner=src
  int* P1 = (int*)carve((size_t)Epp * 4);   // pp src-CSR: partner=dst
  int* P2 = (int*)carve((size_t)Eaa * 4);   // aa dst-CSR
  int* P3 = (int*)carve((size_t)Eaa * 4);   // aa src-CSR
  int* P4 = (int*)carve((size_t)Epa * 4);   // pa dst-CSR (author rows)
  int* P5 = (int*)carve((size_t)Eap * 4);   // ap dst-CSR (paper rows)
  int* SELPP = (int*)carve((size_t)NPAP * 5 * 4);
  int* SELAA = (int*)carve((size_t)NAUT * 5 * 4);

  // ---- CSR build ----
  EdgeJobs ej;
  const int* keys[6]  = {pp_dst, pp_src, aa_dst, aa_src, pa_dst, ap_dst};
  const int* parts[6] = {pp_src, pp_dst, aa_src, aa_dst, pa_src, ap_src};
  int ns[6] = {NPAP, NPAP, NAUT, NAUT, NAUT, NPAP};
  int Es[6] = {Epp, Epp, Eaa, Eaa, Epa, Eap};
  int* outs[6] = {P0, P1, P2, P3, P4, P5};
  int run = 0;
  for (int r = 0; r < 6; r++) {
    ej.key[r] = keys[r]; ej.part[r] = parts[r];
    ej.off[r] = OFF + r * 4097;
    ej.cnt[r] = CNT + r * 4096; ej.cur[r] = CUR + r * 4096;
    ej.out[r] = outs[r];
    ej.eStart[r] = run; run += Es[r];
  }
  ej.eStart[6] = run;
  { int n = 6 * 4096 * 2; zero_int_kernel<<<(n + 255) / 256, 256>>>(CNT, n); }
  count_all<<<(run + 255) / 256, 256>>>(ej, run);
  {
    ScanArgs sa;
    for (int r = 0; r < 6; r++) {
      sa.cnt[r] = CNT + r * 4096; sa.off[r] = OFF + r * 4097; sa.n[r] = ns[r];
    }
    scan_kernel<<<6, 256>>>(sa);
  }
  fill_all<<<(run + 255) / 256, 256>>>(ej, run);

  auto glaunch = [&](GJobs& gj, int njobs, int maxn) {
    dim3 g((maxn + 7) / 8, njobs);
    gather_all<<<g, 256>>>(gj);
  };
  auto makeG = [&](int csr, const float* H, float* o, const int* sel, int n) {
    GJob j; j.off = OFF + csr * 4097; j.part = outs[csr]; j.H = H; j.out = o;
    j.sel = sel; j.n = n; return j;
  };
  auto glaunch2 = [&](GJob a, GJob b) {
    GJobs gj; gj.j[0] = a; gj.j[1] = b;
    glaunch(gj, 2, a.n > b.n ? a.n : b.n);
  };

  // ---- GNN1 ----
  glaunch2(makeG(0, x_p, AGGP, nullptr, NPAP), makeG(2, x_a, AGGA, nullptr, NAUT));
  {
    GemmJobs gs; gs.njobs = 2;
    gs.j[0] = {{x_p, AGGP, nullptr}, {Ws_p0, Wpp0, nullptr}, HP0, NPAP, 128, 2, 1, 0};
    gs.j[1] = {{x_a, AGGA, nullptr}, {Ws_a0, Waa0, nullptr}, HA0, NAUT, 128, 2, 1, 64};
    gemm_all<<<dim3(1, 96), 256>>>(gs);
  }
  glaunch2(makeG(0, HP0, AGGP, nullptr, NPAP), makeG(2, HA0, AGGA, nullptr, NAUT));
  {
    GemmJobs gs; gs.njobs = 2;
    gs.j[0] = {{HP0, AGGP, nullptr}, {Ws_p1, Wpp1, nullptr}, HP1, NPAP, 128, 2, 1, 0};
    gs.j[1] = {{HA0, AGGA, nullptr}, {Ws_a1, Waa1, nullptr}, HA1, NAUT, 128, 2, 1, 64};
    gemm_all<<<dim3(1, 96), 256>>>(gs);
  }
  // ---- edge-MLP projections (N=256) ----
  {
    GemmJobs gs; gs.njobs = 4;
    gs.j[0] = {{HP1, nullptr, nullptr}, {Wep1_pp, nullptr, nullptr}, UP, NPAP, 256, 1, 0, 0};
    gs.j[1] = {{HP1, nullptr, nullptr}, {Wep1_pp + 128 * 256, nullptr, nullptr}, VP, NPAP, 256, 1, 0, 64};
    gs.j[2] = {{HA1, nullptr, nullptr}, {Wep1_aa, nullptr, nullptr}, UA, NAUT, 256, 1, 0, 128};
    gs.j[3] = {{HA1, nullptr, nullptr}, {Wep1_aa + 128 * 256, nullptr, nullptr}, VA, NAUT, 256, 1, 0, 160};
    gemm_all<<<dim3(2, 192), 256>>>(gs);
  }
  // ---- prune (fused pp+aa) ----
  {
    PruneCfg cp = {OFF + 1 * 4097, P1, UP, VP, bep1_pp, Wep2_pp, bep2_pp,
                   4096, kpp0, kpp1, SELPP};
    PruneCfg ca = {OFF + 3 * 4097, P3, UA, VA, bep1_aa, Wep2_aa, bep2_aa,
                   2048, kaa0, kaa1, SELAA};
    prune_all<<<NPAP + NAUT, 128, (4096 + 512) * sizeof(float)>>>(cp, ca, NPAP);
  }
  // ---- outputs: w_pp, w_aa ----
  float* out_f = (float*)d_out;
  w_all<<<(Epp + Eaa + 255) / 256, 256>>>(pp_src, pp_dst, aa_src, aa_dst,
                                          SELPP, SELAA, Epp, Eaa, out_f);
  // ---- GNN2 layer 0 ----
  {
    GJobs gj;
    gj.j[0] = makeG(0, x_p, AGGP, SELPP, NPAP);
    gj.j[1] = makeG(5, x_a, AGGP2, nullptr, NPAP);
    gj.j[2] = makeG(2, x_a, AGGA, SELAA, NAUT);
    gj.j[3] = makeG(4, x_p, AGGA2, nullptr, NAUT);
    glaunch(gj, 4, NPAP);
  }
  {
    GemmJobs gs; gs.njobs = 2;
    gs.j[0] = {{x_p, AGGP, AGGP2}, {Ws_p0, Wpp0, Wap0}, HP0, NPAP, 128, 3, 1, 0};
    gs.j[1] = {{x_a, AGGA, AGGA2}, {Ws_a0, Waa0, Wpa0}, HA0, NAUT, 128, 3, 1, 64};
    gemm_all<<<dim3(1, 96), 256>>>(gs);
  }
  // ---- GNN2 layer 1 (node `index`) + classifier ----
  node_out_kernel<<<1, 128>>>(idxPtr, HP0, HA0,
                              OFF + 0 * 4097, P0, SELPP,
                              OFF + 5 * 4097, P5,
                              Ws_p1, Wpp1, Wap1, Wc, bc, out_f);
}

// round 4
// speedup vs baseline: 1.4956x; 1.0936x over previous
#include <cuda_runtime.h>
#include <cstdint>

#define NPAP 4096
#define NAUT 2048
#define HD   128
#define CANDMAX 1024

// ---------------- threefry2x32 (JAX, 20 rounds) ----------------
__host__ __device__ __forceinline__ void tf2x32(unsigned k0, unsigned k1,
                                                unsigned x0, unsigned x1,
                                                unsigned &o0, unsigned &o1) {
  unsigned ks2 = k0 ^ k1 ^ 0x1BD11BDAu;
  x0 += k0; x1 += k1;
#define TFR(r) { x0 += x1; x1 = (x1 << (r)) | (x1 >> (32 - (r))); x1 ^= x0; }
  TFR(13) TFR(15) TFR(26) TFR(6)  x0 += k1;  x1 += ks2 + 1u;
  TFR(17) TFR(29) TFR(16) TFR(24) x0 += ks2; x1 += k0 + 2u;
  TFR(13) TFR(15) TFR(26) TFR(6)  x0 += k0;  x1 += k1 + 3u;
  TFR(17) TFR(29) TFR(16) TFR(24) x0 += k1;  x1 += ks2 + 4u;
  TFR(13) TFR(15) TFR(26) TFR(6)  x0 += ks2; x1 += k0 + 5u;
#undef TFR
  o0 = x0; o1 = x1;
}
__device__ __forceinline__ unsigned jax_bits(unsigned k0, unsigned k1, unsigned m) {
  unsigned o0, o1; tf2x32(k0, k1, 0u, m, o0, o1); return o0 ^ o1;
}

// ---------------- scratch arena ----------------
__device__ __align__(256) unsigned char g_arena[32u * 1024u * 1024u];

// ---------------- CSR build (fused, x4 vectorized) ----------------
struct EdgeJobs {
  const int* key[6]; const int* part[6];
  const int* off[6]; int* cnt[6]; int* cur[6]; int* out[6];
  int pack[6];
  int eStart[7];
};
__global__ void count_all(EdgeJobs ej, int total) {
  int g4 = (blockIdx.x * blockDim.x + threadIdx.x) * 4;
  if (g4 >= total) return;
  int r = 0;
  while (g4 >= ej.eStart[r + 1]) r++;
  int e = g4 - ej.eStart[r];
  int4 k = *(const int4*)(ej.key[r] + e);
  atomicAdd(&ej.cnt[r][k.x], 1);
  atomicAdd(&ej.cnt[r][k.y], 1);
  atomicAdd(&ej.cnt[r][k.z], 1);
  atomicAdd(&ej.cnt[r][k.w], 1);
}
__global__ void fill_all(EdgeJobs ej, int total) {
  int g4 = (blockIdx.x * blockDim.x + threadIdx.x) * 4;
  if (g4 >= total) return;
  int r = 0;
  while (g4 >= ej.eStart[r + 1]) r++;
  int e = g4 - ej.eStart[r];
  int4 k = *(const int4*)(ej.key[r] + e);
  int4 p = *(const int4*)(ej.part[r] + e);
  int pk = ej.pack[r];
  const int* off = ej.off[r];
  int* cur = ej.cur[r];
  int* out = ej.out[r];
#define DOF(K, P, EE) { int pos = atomicAdd(&cur[K], 1); \
    out[off[K] + pos] = (P) | (pk ? ((EE) << 12) : 0); }
  DOF(k.x, p.x, e)
  DOF(k.y, p.y, e + 1)
  DOF(k.z, p.z, e + 2)
  DOF(k.w, p.w, e + 3)
#undef DOF
}
struct ScanArgs { const int* cnt[6]; int* off[6]; int n[6]; };
__global__ void scan_kernel(ScanArgs a) {
  int b = blockIdx.x;
  const int* cnt = a.cnt[b]; int* off = a.off[b]; int n = a.n[b];
  __shared__ int part[256];
  int t = threadIdx.x, chunk = (n + 255) / 256, st = t * chunk, s = 0;
  for (int j = 0; j < chunk; j++) { int i = st + j; if (i < n) s += cnt[i]; }
  part[t] = s; __syncthreads();
  for (int d = 1; d < 256; d <<= 1) {
    int v = (t >= d) ? part[t - d] : 0;
    __syncthreads(); part[t] += v; __syncthreads();
  }
  int run = (t == 0) ? 0 : part[t - 1];
  for (int j = 0; j < chunk; j++) {
    int i = st + j;
    if (i < n) { off[i] = run; run += cnt[i]; }
  }
  if (t == 255) off[n] = part[255];
}

// ---------------- multi-job mean gather ----------------
struct GJob { const int* off; const int* part; const float* H; float* out;
              const int* sel; int n; };
struct GJobs { GJob j[4]; };
__global__ __launch_bounds__(256) void gather_all(GJobs gj) {
  GJob jb = gj.j[blockIdx.y];
  int node = blockIdx.x * 8 + (threadIdx.x >> 5);
  if (node >= jb.n) return;
  int lane = threadIdx.x & 31;
  int b = jb.off[node], e = jb.off[node + 1];
  float4 acc = make_float4(0.f, 0.f, 0.f, 0.f);
  if (jb.sel) {
    for (int q = b; q < e; ++q) {
      int s = jb.part[q];
      const int* sp = &jb.sel[s * 5];
      if (sp[0] == node || sp[1] == node || sp[2] == node || sp[3] == node ||
          sp[4] == node) {
        float4 v = *((const float4*)(jb.H + (size_t)s * HD) + lane);
        acc.x += v.x; acc.y += v.y; acc.z += v.z; acc.w += v.w;
      }
    }
  } else {
    int q = b;
    for (; q + 4 <= e; q += 4) {
      int s0 = jb.part[q], s1 = jb.part[q + 1];
      int s2 = jb.part[q + 2], s3 = jb.part[q + 3];
      float4 v0 = *((const float4*)(jb.H + (size_t)s0 * HD) + lane);
      float4 v1 = *((const float4*)(jb.H + (size_t)s1 * HD) + lane);
      float4 v2 = *((const float4*)(jb.H + (size_t)s2 * HD) + lane);
      float4 v3 = *((const float4*)(jb.H + (size_t)s3 * HD) + lane);
      acc.x += (v0.x + v1.x) + (v2.x + v3.x);
      acc.y += (v0.y + v1.y) + (v2.y + v3.y);
      acc.z += (v0.z + v1.z) + (v2.z + v3.z);
      acc.w += (v0.w + v1.w) + (v2.w + v3.w);
    }
    for (; q < e; ++q) {
      int s = jb.part[q];
      float4 v = *((const float4*)(jb.H + (size_t)s * HD) + lane);
      acc.x += v.x; acc.y += v.y; acc.z += v.z; acc.w += v.w;
    }
  }
  float inv = 1.f / fmaxf((float)(e - b), 1.f);
  acc.x *= inv; acc.y *= inv; acc.z *= inv; acc.w *= inv;
  *((float4*)(jb.out + (size_t)node * HD) + lane) = acc;
}

// ---------------- multi-job multi-pair GEMM, f32x2, K=128, 64x128 tile ----------------
struct GemmJob { const float* A[3]; const float* B[3]; float* C;
                 int M, N, npairs, relu, rbStart; };
struct GemmJobs { GemmJob j[4]; int njobs; };
__global__ __launch_bounds__(256) void gemm_all(GemmJobs gjs) {
  int by = blockIdx.y;
  int ji = 0;
  while (ji + 1 < gjs.njobs && by >= gjs.j[ji + 1].rbStart) ji++;
  GemmJob jb = gjs.j[ji];
  int row0 = (by - jb.rbStart) * 64;
  int col0 = blockIdx.x * 128;
  if (col0 >= jb.N) return;
  __shared__ float As[16][68];
  __shared__ float Bs[16][132];
  unsigned long long acc[4][4];
#pragma unroll
  for (int i = 0; i < 4; i++)
#pragma unroll
    for (int j = 0; j < 4; j++) acc[i][j] = 0ull;
  int tid = threadIdx.x;
  int ty = tid >> 4, tx = tid & 15;
  for (int p = 0; p < jb.npairs; p++) {
    const float* A = jb.A[p];
    const float* B = jb.B[p];
    for (int kt = 0; kt < 128; kt += 16) {
      {
        int m = tid >> 2, kk = (tid & 3) * 4;
        float4 v = *(const float4*)(A + (size_t)(row0 + m) * 128 + kt + kk);
        As[kk][m] = v.x; As[kk + 1][m] = v.y; As[kk + 2][m] = v.z; As[kk + 3][m] = v.w;
      }
#pragma unroll
      for (int q = 0; q < 2; q++) {
        int li = tid * 2 + q;
        int kk = li >> 5;
        int n4 = (li & 31) * 4;
        float4 v = *(const float4*)(B + (size_t)(kt + kk) * jb.N + col0 + n4);
        Bs[kk][n4] = v.x; Bs[kk][n4 + 1] = v.y; Bs[kk][n4 + 2] = v.z; Bs[kk][n4 + 3] = v.w;
      }
      __syncthreads();
#pragma unroll
      for (int k = 0; k < 16; k++) {
        unsigned long long a2[4], b2[4];
#pragma unroll
        for (int i = 0; i < 4; i++) {
          unsigned ai = __float_as_uint(As[k][ty * 4 + i]);
          asm("mov.b64 %0, {%1, %1};" : "=l"(a2[i]) : "r"(ai));
        }
#pragma unroll
        for (int j = 0; j < 4; j++)
          b2[j] = *(const unsigned long long*)&Bs[k][tx * 8 + j * 2];
#pragma unroll
        for (int i = 0; i < 4; i++)
#pragma unroll
          for (int j = 0; j < 4; j++)
            asm("fma.rn.f32x2 %0, %1, %2, %0;" : "+l"(acc[i][j])
                : "l"(a2[i]), "l"(b2[j]));
      }
      __syncthreads();
    }
  }
#pragma unroll
  for (int i = 0; i < 4; i++) {
    int row = row0 + ty * 4 + i;
#pragma unroll
    for (int j = 0; j < 4; j++) {
      unsigned u0, u1;
      asm("mov.b64 {%0, %1}, %2;" : "=r"(u0), "=r"(u1) : "l"(acc[i][j]));
      float c0 = __uint_as_float(u0), c1 = __uint_as_float(u1);
      if (jb.relu) { c0 = fmaxf(c0, 0.f); c1 = fmaxf(c1, 0.f); }
      float2* cp = (float2*)(jb.C + (size_t)row * jb.N + col0 + tx * 8 + j * 2);
      *cp = make_float2(c0, c1);
    }
  }
}

// ---------------- prune: edge MLP + coalesce + compact gumbel top-5 + w out ----------------
__device__ __forceinline__ unsigned long long packkey(float v, int j) {
  unsigned u = __float_as_uint(v);
  u = (u >> 31) ? ~u : (u | 0x80000000u);
  return (((unsigned long long)u) << 32) |
         (unsigned long long)(0xFFFFFFFFu - (unsigned)j);
}
struct PruneCfg {
  const int* roff; const int* rpart;
  const float* U; const float* V;
  const float* b1; const float* W2; const float* b2;
  int Nc; unsigned k0, k1; int* sel; float* outW;
};
__global__ __launch_bounds__(256) void prune_all(PruneCfg cp, PruneCfg ca, int nPP) {
  PruneCfg cfg = (blockIdx.x < nPP) ? cp : ca;
  int i = (blockIdx.x < nPP) ? blockIdx.x : blockIdx.x - nPP;
  extern __shared__ float sm[];
  float* Arow = sm;                           // Nc
  float* Urow = sm + cfg.Nc;                  // 256
  float* W2c  = Urow + 256;                   // 256
  unsigned long long* cand = (unsigned long long*)(W2c + 256);  // CANDMAX
  __shared__ unsigned long long red[8];
  __shared__ int sel5[5];
  __shared__ int ncand;
  int t = threadIdx.x, warp = t >> 5, lane = t & 31;
  if (t == 0) ncand = 0;
  Urow[t] = cfg.U[(size_t)i * 256 + t] + cfg.b1[t];
  W2c[t] = cfg.W2[2 * t];
  for (int j = t; j < cfg.Nc; j += 256) Arow[j] = 0.f;
  __syncthreads();

  int b = cfg.roff[i], nE = cfg.roff[i + 1] - b;
  float b2v = cfg.b2[0];
  const float4* U4 = (const float4*)&Urow[lane * 8];
  const float4* W4 = (const float4*)&W2c[lane * 8];
  float4 u0 = U4[0], u1 = U4[1], w0 = W4[0], w1 = W4[1];
  for (int e = warp; e < nE; e += 8) {
    int p = cfg.rpart[b + e];
    int d = p & 4095;
    const float4* V4 = (const float4*)(cfg.V + (size_t)d * 256) + lane * 2;
    float4 v0 = V4[0], v1 = V4[1];
    float acc = fmaxf(u0.x + v0.x, 0.f) * w0.x + fmaxf(u0.y + v0.y, 0.f) * w0.y +
                fmaxf(u0.z + v0.z, 0.f) * w0.z + fmaxf(u0.w + v0.w, 0.f) * w0.w +
                fmaxf(u1.x + v1.x, 0.f) * w1.x + fmaxf(u1.y + v1.y, 0.f) * w1.y +
                fmaxf(u1.z + v1.z, 0.f) * w1.z + fmaxf(u1.w + v1.w, 0.f) * w1.w;
#pragma unroll
    for (int o = 16; o; o >>= 1) acc += __shfl_xor_sync(0xffffffffu, acc, o);
    if (lane == 0) atomicAdd(&Arow[d], acc + b2v);
  }
  __syncthreads();

  // candidates: masked entries (A>0) get gumbel noise
  for (int j = t; j < cfg.Nc; j += 256) {
    float a = Arow[j];
    if (a > 0.f) {
      unsigned m = (unsigned)i * (unsigned)cfg.Nc + (unsigned)j;
      unsigned bits = jax_bits(cfg.k0, cfg.k1, m);
      float f = __uint_as_float((bits >> 9) | 0x3f800000u) - 1.0f;
      float u = fmaxf(1e-10f, f + 1e-10f);
      float y = a + (-logf(-logf(u)));
      int pos = atomicAdd(&ncand, 1);
      if (pos < CANDMAX) cand[pos] = packkey(y, j);
    }
  }
  __syncthreads();
  int nc = ncand < CANDMAX ? ncand : CANDMAX;

  unsigned long long prev = 0;
  for (int r = 0; r < 5; r++) {
    unsigned long long best = 0ull;
    for (int q = t; q < nc; q += 256) {
      unsigned long long k = cand[q];
      if (k == prev) { cand[q] = 0ull; k = 0ull; }
      if (k > best) best = k;
    }
#pragma unroll
    for (int o = 16; o; o >>= 1) {
      unsigned long long v = __shfl_xor_sync(0xffffffffu, best, o);
      if (v > best) best = v;
    }
    if (lane == 0) red[warp] = best;
    __syncthreads();
    if (t == 0) {
      unsigned long long w = red[0];
      for (int q = 1; q < 8; q++) if (red[q] > w) w = red[q];
      red[0] = w;
      sel5[r] = (w != 0ull) ? (int)(0xFFFFFFFFu - (unsigned)(w & 0xFFFFFFFFull)) : -1;
    }
    __syncthreads();
    prev = red[0];
    __syncthreads();
  }
  // fallback: ties among masked (-1e9) entries resolve to ascending index
  if (t == 0) {
    int r = 0;
    while (r < 5 && sel5[r] >= 0) r++;
    for (int j = 0; j < cfg.Nc && r < 5; j++)
      if (!(Arow[j] > 0.f)) sel5[r++] = j;
    for (int q = 0; q < 5; q++) cfg.sel[i * 5 + q] = sel5[q];
  }
  __syncthreads();

  int s0 = sel5[0], s1 = sel5[1], s2 = sel5[2], s3 = sel5[3], s4 = sel5[4];
  for (int e = t; e < nE; e += 256) {
    int p = cfg.rpart[b + e];
    int d = p & 4095;
    int eid = p >> 12;
    cfg.outW[eid] = (d == s0 || d == s1 || d == s2 || d == s3 || d == s4) ? 1.f : 0.f;
  }
}

// ---------------- GNN2 layer1 for node `index` + classifier ----------------
__global__ __launch_bounds__(128) void node_out_kernel(
    const int* __restrict__ idxPtr,
    const float* __restrict__ HP0, const float* __restrict__ HA0,
    const int* __restrict__ ppoff, const int* __restrict__ pppart,
    const int* __restrict__ selpp,
    const int* __restrict__ apoff, const int* __restrict__ appart,
    const float* __restrict__ Wself, const float* __restrict__ Wpp1,
    const float* __restrict__ Wap1,
    const float* __restrict__ Wc, const float* __restrict__ bc,
    float* __restrict__ out) {
  __shared__ float selfv[128], mpp[128], mapv[128], agg[128];
  int t = threadIdx.x;
  int idx = idxPtr[0];
  selfv[t] = HP0[(size_t)idx * HD + t];
  int b = ppoff[idx], e = ppoff[idx + 1];
  float s = 0.f;
  for (int q = b; q < e; q++) {
    int sn = pppart[q];
    const int* sp = &selpp[sn * 5];
    if (sp[0] == idx || sp[1] == idx || sp[2] == idx || sp[3] == idx || sp[4] == idx)
      s += HP0[(size_t)sn * HD + t];
  }
  mpp[t] = s / fmaxf((float)(e - b), 1.f);
  b = apoff[idx]; e = apoff[idx + 1];
  s = 0.f;
  for (int q = b; q < e; q++) s += HA0[(size_t)appart[q] * HD + t];
  mapv[t] = s / fmaxf((float)(e - b), 1.f);
  __syncthreads();
  float a = 0.f;
  for (int k = 0; k < HD; k++)
    a += selfv[k] * Wself[k * HD + t] + mpp[k] * Wpp1[k * HD + t] +
         mapv[k] * Wap1[k * HD + t];
  agg[t] = fmaxf(a, 0.f);
  __syncthreads();
  if (t < 5) {
    float y = bc[t];
    for (int k = 0; k < HD; k++) y += agg[k] * Wc[k * 5 + t];
    out[t] = y;
  }
}

// ---------------- host launcher ----------------
extern "C" void kernel_launch(void* const* d_in, const int* in_sizes, int n_in,
                              void* d_out, int out_size) {
  const float* x_p = (const float*)d_in[0];
  const float* x_a = (const float*)d_in[1];
  const int* ei_pp = (const int*)d_in[2];
  const int* ei_aa = (const int*)d_in[3];
  const int* ei_pa = (const int*)d_in[4];
  const int* ei_ap = (const int*)d_in[5];
  const int* idxPtr = (const int*)d_in[8];
  const float* Ws_p0 = (const float*)d_in[9];
  const float* Ws_p1 = (const float*)d_in[10];
  const float* Ws_a0 = (const float*)d_in[11];
  const float* Ws_a1 = (const float*)d_in[12];
  const float* Wpp0 = (const float*)d_in[13];
  const float* Wpp1 = (const float*)d_in[14];
  const float* Waa0 = (const float*)d_in[15];
  const float* Waa1 = (const float*)d_in[16];
  const float* Wpa0 = (const float*)d_in[17];
  const float* Wap0 = (const float*)d_in[19];
  const float* Wap1 = (const float*)d_in[20];
  const float* Wep1_pp = (const float*)d_in[21];
  const float* bep1_pp = (const float*)d_in[22];
  const float* Wep2_pp = (const float*)d_in[23];
  const float* bep2_pp = (const float*)d_in[24];
  const float* Wep1_aa = (const float*)d_in[25];
  const float* bep1_aa = (const float*)d_in[26];
  const float* Wep2_aa = (const float*)d_in[27];
  const float* bep2_aa = (const float*)d_in[28];
  const float* Wc = (const float*)d_in[29];
  const float* bc = (const float*)d_in[30];

  int Epp = in_sizes[2] / 2, Eaa = in_sizes[3] / 2;
  int Epa = in_sizes[4] / 2, Eap = in_sizes[5] / 2;
  const int* pp_src = ei_pp;  const int* pp_dst = ei_pp + Epp;
  const int* aa_src = ei_aa;  const int* aa_dst = ei_aa + Eaa;
  const int* pa_src = ei_pa;  const int* pa_dst = ei_pa + Epa;
  const int* ap_src = ei_ap;  const int* ap_dst = ei_ap + Eap;

  unsigned kpp0, kpp1, kaa0, kaa1;
  tf2x32(0u, 42u, 0u, 0u, kpp0, kpp1);
  tf2x32(0u, 42u, 0u, 1u, kaa0, kaa1);

  void* basep = nullptr;
  cudaGetSymbolAddress(&basep, g_arena);
  unsigned char* ar = (unsigned char*)basep;
  size_t off = 0;
  auto carve = [&](size_t bytes) -> unsigned char* {
    unsigned char* p = ar + off;
    off += (bytes + 255) & ~(size_t)255;
    return p;
  };
  float* AGGP  = (float*)carve((size_t)NPAP * HD * 4);
  float* AGGA  = (float*)carve((size_t)NAUT * HD * 4);
  float* AGGP2 = (float*)carve((size_t)NPAP * HD * 4);
  float* AGGA2 = (float*)carve((size_t)NAUT * HD * 4);
  float* HP0 = (float*)carve((size_t)NPAP * HD * 4);
  float* HP1 = (float*)carve((size_t)NPAP * HD * 4);
  float* HA0 = (float*)carve((size_t)NAUT * HD * 4);
  float* HA1 = (float*)carve((size_t)NAUT * HD * 4);
  float* UP = (float*)carve((size_t)NPAP * 256 * 4);
  float* VP = (float*)carve((size_t)NPAP * 256 * 4);
  float* UA = (float*)carve((size_t)NAUT * 256 * 4);
  float* VA = (float*)carve((size_t)NAUT * 256 * 4);
  int* CNT = (int*)carve(6 * 4096 * 4);
  int* CUR = (int*)carve(6 * 4096 * 4);
  int* OFF = (int*)carve(6 * 4097 * 4);
  int* P0 = (int*)carve((size_t)Epp * 4);   // pp dst-CSR: partner=src
  int* P1 = (int*)carve((size_t)Epp * 4);   // pp src-CSR: packed dst|eid<<12
  int* P2 = (int*)carve((size_t)Eaa * 4);   // aa dst-CSR
  int* P3 = (int*)carve((size_t)Eaa * 4);   // aa src-CSR: packed
  int* P4 = (int*)carve((size_t)Epa * 4);   // pa dst-CSR
  int* P5 = (int*)carve((size_t)Eap * 4);   // ap dst-CSR
  int* SELPP = (int*)carve((size_t)NPAP * 5 * 4);
  int* SELAA = (int*)carve((size_t)NAUT * 5 * 4);

  // ---- CSR build ----
  EdgeJobs ej;
  const int* keys[6]  = {pp_dst, pp_src, aa_dst, aa_src, pa_dst, ap_dst};
  const int* parts[6] = {pp_src, pp_dst, aa_src, aa_dst, pa_src, ap_src};
  int ns[6] = {NPAP, NPAP, NAUT, NAUT, NAUT, NPAP};
  int Es[6] = {Epp, Epp, Eaa, Eaa, Epa, Eap};
  int packs[6] = {0, 1, 0, 1, 0, 0};
  int* outs[6] = {P0, P1, P2, P3, P4, P5};
  int run = 0;
  for (int r = 0; r < 6; r++) {
    ej.key[r] = keys[r]; ej.part[r] = parts[r];
    ej.off[r] = OFF + r * 4097;
    ej.cnt[r] = CNT + r * 4096; ej.cur[r] = CUR + r * 4096;
    ej.out[r] = outs[r]; ej.pack[r] = packs[r];
    ej.eStart[r] = run; run += Es[r];
  }
  ej.eStart[6] = run;
  cudaMemsetAsync(CNT, 0, 2 * 6 * 4096 * 4);   // CNT+CUR contiguous
  {
    int th = run / 4;
    count_all<<<(th + 255) / 256, 256>>>(ej, run);
  }
  {
    ScanArgs sa;
    for (int r = 0; r < 6; r++) {
      sa.cnt[r] = CNT + r * 4096; sa.off[r] = OFF + r * 4097; sa.n[r] = ns[r];
    }
    scan_kernel<<<6, 256>>>(sa);
  }
  {
    int th = run / 4;
    fill_all<<<(th + 255) / 256, 256>>>(ej, run);
  }

  auto glaunch = [&](GJobs& gj, int njobs, int maxn) {
    dim3 g((maxn + 7) / 8, njobs);
    gather_all<<<g, 256>>>(gj);
  };
  auto makeG = [&](int csr, const float* H, float* o, const int* sel, int n) {
    GJob j; j.off = OFF + csr * 4097; j.part = outs[csr]; j.H = H; j.out = o;
    j.sel = sel; j.n = n; return j;
  };
  auto glaunch2 = [&](GJob a, GJob b) {
    GJobs gj; gj.j[0] = a; gj.j[1] = b;
    glaunch(gj, 2, a.n > b.n ? a.n : b.n);
  };

  // ---- GNN1 ----
  glaunch2(makeG(0, x_p, AGGP, nullptr, NPAP), makeG(2, x_a, AGGA, nullptr, NAUT));
  {
    GemmJobs gs; gs.njobs = 2;
    gs.j[0] = {{x_p, AGGP, nullptr}, {Ws_p0, Wpp0, nullptr}, HP0, NPAP, 128, 2, 1, 0};
    gs.j[1] = {{x_a, AGGA, nullptr}, {Ws_a0, Waa0, nullptr}, HA0, NAUT, 128, 2, 1, 64};
    gemm_all<<<dim3(1, 96), 256>>>(gs);
  }
  glaunch2(makeG(0, HP0, AGGP, nullptr, NPAP), makeG(2, HA0, AGGA, nullptr, NAUT));
  {
    GemmJobs gs; gs.njobs = 2;
    gs.j[0] = {{HP0, AGGP, nullptr}, {Ws_p1, Wpp1, nullptr}, HP1, NPAP, 128, 2, 1, 0};
    gs.j[1] = {{HA0, AGGA, nullptr}, {Ws_a1, Waa1, nullptr}, HA1, NAUT, 128, 2, 1, 64};
    gemm_all<<<dim3(1, 96), 256>>>(gs);
  }
  // ---- edge-MLP projections (N=256) ----
  {
    GemmJobs gs; gs.njobs = 4;
    gs.j[0] = {{HP1, nullptr, nullptr}, {Wep1_pp, nullptr, nullptr}, UP, NPAP, 256, 1, 0, 0};
    gs.j[1] = {{HP1, nullptr, nullptr}, {Wep1_pp + 128 * 256, nullptr, nullptr}, VP, NPAP, 256, 1, 0, 64};
    gs.j[2] = {{HA1, nullptr, nullptr}, {Wep1_aa, nullptr, nullptr}, UA, NAUT, 256, 1, 0, 128};
    gs.j[3] = {{HA1, nullptr, nullptr}, {Wep1_aa + 128 * 256, nullptr, nullptr}, VA, NAUT, 256, 1, 0, 160};
    gemm_all<<<dim3(2, 192), 256>>>(gs);
  }
  // ---- prune (fused pp+aa, writes sel + w outputs) ----
  float* out_f = (float*)d_out;
  {
    PruneCfg cp = {OFF + 1 * 4097, P1, UP, VP, bep1_pp, Wep2_pp, bep2_pp,
                   4096, kpp0, kpp1, SELPP, out_f + 5};
    PruneCfg ca = {OFF + 3 * 4097, P3, UA, VA, bep1_aa, Wep2_aa, bep2_aa,
                   2048, kaa0, kaa1, SELAA, out_f + 5 + Epp};
    size_t smem = (4096 + 512) * sizeof(float) + CANDMAX * 8;
    prune_all<<<NPAP + NAUT, 256, smem>>>(cp, ca, NPAP);
  }
  // ---- GNN2 layer 0 ----
  {
    GJobs gj;
    gj.j[0] = makeG(0, x_p, AGGP, SELPP, NPAP);
    gj.j[1] = makeG(5, x_a, AGGP2, nullptr, NPAP);
    gj.j[2] = makeG(2, x_a, AGGA, SELAA, NAUT);
    gj.j[3] = makeG(4, x_p, AGGA2, nullptr, NAUT);
    glaunch(gj, 4, NPAP);
  }
  {
    GemmJobs gs; gs.njobs = 2;
    gs.j[0] = {{x_p, AGGP, AGGP2}, {Ws_p0, Wpp0, Wap0}, HP0, NPAP, 128, 3, 1, 0};
    gs.j[1] = {{x_a, AGGA, AGGA2}, {Ws_a0, Waa0, Wpa0}, HA0, NAUT, 128, 3, 1, 64};
    gemm_all<<<dim3(1, 96), 256>>>(gs);
  }
  // ---- GNN2 layer 1 (node `index`) + classifier ----
  node_out_kernel<<<1, 128>>>(idxPtr, HP0, HA0,
                              OFF + 0 * 4097, P0, SELPP,
                              OFF + 5 * 4097, P5,
                              Ws_p1, Wpp1, Wap1, Wc, bc, out_f);
}